// round 9
// baseline (speedup 1.0000x reference)
#include <cuda_runtime.h>
#include <cuda_fp16.h>
#include <cstdint>

// Problem constants (fixed by the dataset)
#define IN_F   4096
#define OUT_F  11008
#define GROUPS 32       // IN_F / 128
#define BM 128
#define BN 128
#define BK 64           // k-halves per stage
#define STAGES 4
#define KT (IN_F / BK)  // 64

#define A_ST   16384    // BM * 128 bytes (fp16, SW128)
#define BP_ST  4096     // BN * 32 bytes (packed nibbles)
#define BP_OFF (STAGES * A_ST)             // 65536
#define T_OFF  (BP_OFF + STAGES * BP_ST)   // 81920
#define SMEM_TOTAL (T_OFF + 16384)         // 98304 (96KB/CTA, 2 CTAs/SM)

// Activations converted to fp16, [M][IN_F].
__device__ __half g_X[(size_t)4096 * IN_F];
// qweight repacked to true bytes: g_Wp[o*2048 + j] = low byte of qweight int32.
__device__ uint8_t g_Wp[(size_t)OUT_F * (IN_F / 2)];

// ---------------------------------------------------------------------------
// Convert x (float32, fp16-valued) -> fp16 in g_X. 8 elements / thread.
// ---------------------------------------------------------------------------
__global__ void convert_kernel(const float4* __restrict__ xin, int n) {
    int i = (blockIdx.x * blockDim.x + threadIdx.x) * 8;
    if (i >= n) return;
    float4 a = xin[i / 4];
    float4 b = xin[i / 4 + 1];
    __half2 h[4];
    h[0] = __floats2half2_rn(a.x, a.y);
    h[1] = __floats2half2_rn(a.z, a.w);
    h[2] = __floats2half2_rn(b.x, b.y);
    h[3] = __floats2half2_rn(b.z, b.w);
    *reinterpret_cast<uint4*>(g_X + i) = *reinterpret_cast<uint4*>(h);
}

// ---------------------------------------------------------------------------
// Repack qweight: int32 (one byte-value each) -> dense bytes. 16 in / thread.
// ---------------------------------------------------------------------------
__global__ void repack_kernel(const int4* __restrict__ qw) {
    int i = blockIdx.x * blockDim.x + threadIdx.x;   // 16-byte output chunk id
    const int total = OUT_F * (IN_F / 2) / 16;       // 1,409,024
    if (i >= total) return;
    uint8_t out[16];
#pragma unroll
    for (int t = 0; t < 4; t++) {
        int4 v = qw[i * 4 + t];
        out[t * 4 + 0] = (uint8_t)v.x;
        out[t * 4 + 1] = (uint8_t)v.y;
        out[t * 4 + 2] = (uint8_t)v.z;
        out[t * 4 + 3] = (uint8_t)v.w;
    }
    *reinterpret_cast<uint4*>(g_Wp + (size_t)i * 16) =
        *reinterpret_cast<uint4*>(out);
}

// ---------------------------------------------------------------------------
__device__ __forceinline__ uint32_t sw128(uint32_t o) {
    return o ^ ((o >> 3) & 0x70);
}

__device__ __forceinline__ void cp_async16(uint32_t saddr, const void* gptr) {
    asm volatile("cp.async.cg.shared.global [%0], [%1], 16;\n"
                 :: "r"(saddr), "l"(gptr) : "memory");
}

// A stage: 128 rows x 128B (SW128). 1024 chunks / 128 thr = 8 each.
__device__ __forceinline__ void load_A(uint32_t sA, const __half* __restrict__ Ag,
                                       int m0, int k0, int tid) {
#pragma unroll
    for (int i = 0; i < 8; i++) {
        int chunk = tid + i * 128;
        int r = chunk >> 3;
        int c = chunk & 7;
        cp_async16(sA + sw128((uint32_t)(r * 128 + c * 16)),
                   Ag + (size_t)(m0 + r) * IN_F + k0 + c * 8);
    }
}

// Bp stage: 128 rows x 32B packed nibbles, 16B-unit swizzle on (r>>2)&1.
__device__ __forceinline__ void load_Bp(uint32_t sBp,
                                        const uint8_t* __restrict__ qwb,
                                        int n0, int kt, int tid) {
#pragma unroll
    for (int i = 0; i < 2; i++) {
        int chunk = tid + i * 128;
        int r = chunk >> 1;
        int c = chunk & 1;
        uint32_t dst = sBp + r * 32 + ((c ^ ((r >> 2) & 1)) << 4);
        cp_async16(dst, qwb + (size_t)(n0 + r) * (IN_F / 2) + kt * 32 + c * 16);
    }
}

// A fragments for one ks step (4 x ldmatrix.x4)
__device__ __forceinline__ void load_afrags(uint32_t sA, int ks, int wm, int lane,
                                            uint32_t a[4][4]) {
    const int cb = ks * 32 + ((lane >> 4) << 4);
#pragma unroll
    for (int mf = 0; mf < 4; mf++) {
        int r = wm * 64 + mf * 16 + (lane & 15);
        uint32_t addr = sA + sw128((uint32_t)(r * 128 + cb));
        asm volatile(
            "ldmatrix.sync.aligned.m8n8.x4.shared.b16 {%0,%1,%2,%3}, [%4];\n"
            : "=r"(a[mf][0]), "=r"(a[mf][1]), "=r"(a[mf][2]), "=r"(a[mf][3])
            : "r"(addr));
    }
}

// ---------------------------------------------------------------------------
// Fused GEMM: C[M][OUT_F](f32) = g_X (f16) x dequant4(g_Wp)^T
// BM=BN=128, 4 warps (wm 0..1 x wn 0..1), warp tile 64x64, 2 CTAs/SM,
// 4-stage cp.async; B dequantized from nibbles directly into mma fragments.
// ---------------------------------------------------------------------------
__global__ void __launch_bounds__(128, 2)
gemm_kernel(float* __restrict__ C,
            const float* __restrict__ scales,
            const int* __restrict__ qz) {
    extern __shared__ char smem[];
    const __half* __restrict__ A = g_X;
    const uint8_t* __restrict__ qwb = g_Wp;

    const int tid  = threadIdx.x;
    const int lane = tid & 31;
    const int warp = tid >> 5;
    const int wm   = warp & 1;
    const int wn   = warp >> 1;
    const int m0   = blockIdx.x * BM;
    const int n0   = blockIdx.y * BN;

    uint32_t sb  = (uint32_t)__cvta_generic_to_shared(smem);
    uint32_t* tbl = reinterpret_cast<uint32_t*>(smem + T_OFF);

    // Build per-row scale/zero table: tbl[g*128 + r] = (hz16 << 16) | hs16
    // hz = fp16 bits of (1024 + z) = 0x6400 + z ; hs = fp16(scale).
    {
        int o = n0 + tid;
        const int* qzrow = qz + o * (GROUPS / 2);
        const float* srow = scales + (size_t)o * GROUPS;
#pragma unroll 4
        for (int g = 0; g < GROUPS; g++) {
            float s = srow[g];
            int zb = qzrow[g >> 1];
            int z  = (g & 1) ? ((zb >> 4) & 15) : (zb & 15);
            uint32_t hs = (uint32_t)__half_as_ushort(__float2half_rn(s));
            uint32_t hz = 0x6400u + (uint32_t)z;
            tbl[g * 128 + tid] = (hz << 16) | hs;
        }
    }

    float acc[4][8][4];
#pragma unroll
    for (int i = 0; i < 4; i++)
#pragma unroll
        for (int j = 0; j < 8; j++)
#pragma unroll
            for (int k = 0; k < 4; k++) acc[i][j][k] = 0.0f;

    // Prologue: fill STAGES-1 stages
#pragma unroll
    for (int s = 0; s < STAGES - 1; s++) {
        load_A(sb + s * A_ST, A, m0, s * BK, tid);
        load_Bp(sb + BP_OFF + s * BP_ST, qwb, n0, s, tid);
        asm volatile("cp.async.commit_group;\n" ::: "memory");
    }

    const uint32_t psel = 0x4440u | (uint32_t)(lane & 3);
    uint32_t a[2][4][4];

    for (int kt = 0; kt < KT; kt++) {
        asm volatile("cp.async.wait_group 2;\n" ::: "memory");
        __syncthreads();

        int kn = kt + STAGES - 1;
        if (kn < KT) {
            int sn = kn % STAGES;
            load_A(sb + sn * A_ST, A, m0, kn * BK, tid);
            load_Bp(sb + BP_OFF + sn * BP_ST, qwb, n0, kn, tid);
        }
        asm volatile("cp.async.commit_group;\n" ::: "memory");

        const int st = kt % STAGES;
        uint32_t sA  = sb + st * A_ST;
        const char* bp = smem + BP_OFF + st * BP_ST;

        // scale/zero pairs for this kt's group
        const int g = kt >> 1;
        uint32_t sp[8];
#pragma unroll
        for (int nf = 0; nf < 8; nf++) {
            int row = wn * 64 + nf * 8 + (lane >> 2);
            sp[nf] = tbl[g * 128 + row];
        }

        load_afrags(sA, 0, wm, lane, a[0]);
#pragma unroll
        for (int ks = 0; ks < 4; ks++) {
            int cur = ks & 1;
            if (ks < 3)
                load_afrags(sA, ks + 1, wm, lane, a[cur ^ 1]);

            // Dequantize B fragments for this ks
            uint32_t b[8][2];
#pragma unroll
            for (int nf = 0; nf < 8; nf++) {
                int row = wn * 64 + nf * 8 + (lane >> 2);
                uint32_t off = (uint32_t)(row * 32)
                             + ((((uint32_t)ks >> 1) ^ ((row >> 2) & 1)) << 4)
                             + ((ks & 1) << 3);
                uint2 v = *reinterpret_cast<const uint2*>(bp + off);
                uint32_t s2 = __byte_perm(sp[nf], sp[nf], 0x1010);
                uint32_t z2 = __byte_perm(sp[nf], sp[nf], 0x3232);
                __half2 s2h = *reinterpret_cast<__half2*>(&s2);
                __half2 z2h = *reinterpret_cast<__half2*>(&z2);

                uint32_t e0 = __byte_perm(v.x, 0u, psel);
                uint32_t t0 = (((e0 << 12) | e0) & 0x000F000Fu) | 0x64006400u;
                __half2 w0 = __hmul2(__hsub2(*reinterpret_cast<__half2*>(&t0), z2h), s2h);
                b[nf][0] = *reinterpret_cast<uint32_t*>(&w0);

                uint32_t e1 = __byte_perm(v.y, 0u, psel);
                uint32_t t1 = (((e1 << 12) | e1) & 0x000F000Fu) | 0x64006400u;
                __half2 w1 = __hmul2(__hsub2(*reinterpret_cast<__half2*>(&t1), z2h), s2h);
                b[nf][1] = *reinterpret_cast<uint32_t*>(&w1);
            }

#pragma unroll
            for (int mf = 0; mf < 4; mf++) {
#pragma unroll
                for (int nf = 0; nf < 8; nf++) {
                    float* c = acc[mf][nf];
                    asm volatile(
                        "mma.sync.aligned.m16n8k16.row.col.f32.f16.f16.f32 "
                        "{%0,%1,%2,%3}, {%4,%5,%6,%7}, {%8,%9}, {%0,%1,%2,%3};\n"
                        : "+f"(c[0]), "+f"(c[1]), "+f"(c[2]), "+f"(c[3])
                        : "r"(a[cur][mf][0]), "r"(a[cur][mf][1]),
                          "r"(a[cur][mf][2]), "r"(a[cur][mf][3]),
                          "r"(b[nf][0]), "r"(b[nf][1]));
                }
            }
        }
    }

    // Epilogue: direct f32 stores (float2), every element covered.
#pragma unroll
    for (int mf = 0; mf < 4; mf++) {
#pragma unroll
        for (int nf = 0; nf < 8; nf++) {
            int m = m0 + wm * 64 + mf * 16 + (lane >> 2);
            int n = n0 + wn * 64 + nf * 8 + (lane & 3) * 2;
            float2* p0 = reinterpret_cast<float2*>(C + (size_t)m * OUT_F + n);
            *p0 = make_float2(acc[mf][nf][0], acc[mf][nf][1]);
            float2* p1 = reinterpret_cast<float2*>(C + (size_t)(m + 8) * OUT_F + n);
            *p1 = make_float2(acc[mf][nf][2], acc[mf][nf][3]);
        }
    }
}

// ---------------------------------------------------------------------------
extern "C" void kernel_launch(void* const* d_in, const int* in_sizes, int n_in,
                              void* d_out, int out_size) {
    (void)n_in; (void)out_size;
    float* out = (float*)d_out;   // [M, OUT_F] f32

    const int n_x = in_sizes[0];            // x element count (f32)
    const int M   = n_x / IN_F;             // 4096

    // 1) Convert x (f32) -> fp16 g_X
    convert_kernel<<<(n_x / 8 + 255) / 256, 256>>>(
        (const float4*)d_in[0], n_x);

    // 2) Repack qweight int32 -> dense packed bytes g_Wp
    {
        int total = OUT_F * (IN_F / 2) / 16;
        repack_kernel<<<(total + 255) / 256, 256>>>((const int4*)d_in[1]);
    }

    // 3) Fused dequant + tensor-core GEMM (2 CTAs/SM)
    cudaFuncSetAttribute(gemm_kernel,
                         cudaFuncAttributeMaxDynamicSharedMemorySize,
                         SMEM_TOTAL);
    dim3 grid(M / BM, OUT_F / BN);   // (32, 86): M fastest -> N-band L2 reuse
    gemm_kernel<<<grid, 128, SMEM_TOTAL>>>(
        out, (const float*)d_in[2], (const int*)d_in[3]);
}

// round 10
// speedup vs baseline: 1.1341x; 1.1341x over previous
#include <cuda_runtime.h>
#include <cuda_fp16.h>
#include <cstdint>

// Problem constants (fixed by the dataset)
#define IN_F   4096
#define OUT_F  11008
#define GROUPS 32       // IN_F / 128
#define BM 128
#define BN 128
#define BK 64           // k-halves per stage (128 bytes per row)
#define STAGES 3
#define STAGE_A_BYTES (BM * 128)                       // 16384
#define STAGE_BYTES   (STAGE_A_BYTES + BN * 128)       // 32768
#define KT (IN_F / BK)  // 64

// Dequantized weights, fp16, [OUT_F][IN_F] row-major (K contiguous).
__device__ __half g_W[(size_t)OUT_F * IN_F];
// Activations converted to fp16, [M][IN_F].
__device__ __half g_X[(size_t)4096 * IN_F];

// ---------------------------------------------------------------------------
// Fused prep: blocks [0, nconv) convert x f32->fp16; the rest dequantize W.
// ---------------------------------------------------------------------------
__global__ void prep_kernel(const float4* __restrict__ xin, int n_x, int nconv,
                            const int4* __restrict__ qw,
                            const float* __restrict__ scales,
                            const int* __restrict__ qz) {
    if ((int)blockIdx.x < nconv) {
        int i = (blockIdx.x * blockDim.x + threadIdx.x) * 8;
        if (i >= n_x) return;
        float4 a = xin[i / 4];
        float4 b = xin[i / 4 + 1];
        __half2 h[4];
        h[0] = __floats2half2_rn(a.x, a.y);
        h[1] = __floats2half2_rn(a.z, a.w);
        h[2] = __floats2half2_rn(b.x, b.y);
        h[3] = __floats2half2_rn(b.z, b.w);
        *reinterpret_cast<uint4*>(g_X + i) = *reinterpret_cast<uint4*>(h);
    } else {
        const int JP = IN_F / 8;  // 512 int4-chunks per output row
        int idx = (blockIdx.x - nconv) * blockDim.x + threadIdx.x;
        if (idx >= OUT_F * JP) return;

        int o  = idx / JP;
        int jq = idx - o * JP;
        int g  = jq >> 4;           // group = (jq*8)/128

        int4 v = qw[idx];
        int zb = qz[o * (GROUPS / 2) + (g >> 1)];
        int z  = (g & 1) ? ((zb >> 4) & 15) : (zb & 15);
        float s = scales[o * GROUPS + g];

        int q[4] = {v.x, v.y, v.z, v.w};
        __half2 h[4];
#pragma unroll
        for (int t = 0; t < 4; t++) {
            float w0 = (float)((q[t] & 15) - z) * s;
            float w1 = (float)(((q[t] >> 4) & 15) - z) * s;
            h[t] = __floats2half2_rn(w0, w1);
        }
        *reinterpret_cast<uint4*>(g_W + (size_t)idx * 8) = *reinterpret_cast<uint4*>(h);
    }
}

// ---------------------------------------------------------------------------
// GEMM: C[M][OUT_F] (f32) = A[M][IN_F] (f16) * W^T
// TN mma.sync.m16n8k16. BM=BN=128 BK=64, 3-stage cp.async, SW128 smem,
// 4 warps (2x2), warp tile 64x64, 2 CTAs/SM, reg fragment pipelining,
// split named barrier (arrive after last smem read, sync at loop top).
// ---------------------------------------------------------------------------
__device__ __forceinline__ uint32_t sw128(uint32_t o) {
    return o ^ ((o >> 3) & 0x70);
}

__device__ __forceinline__ void cp_async16(uint32_t saddr, const void* gptr) {
    asm volatile("cp.async.cg.shared.global [%0], [%1], 16;\n"
                 :: "r"(saddr), "l"(gptr) : "memory");
}

// Load one k-stage: A 128x64h (1024 16B chunks) + B 128x64h (1024). 128 thr.
__device__ __forceinline__ void load_tiles(uint32_t sA,
                                           const __half* __restrict__ Ag,
                                           const __half* __restrict__ Bg,
                                           int m0, int n0, int k0, int tid) {
    uint32_t sB = sA + STAGE_A_BYTES;
#pragma unroll
    for (int i = 0; i < 8; i++) {
        int chunk = tid + i * 128;
        int r = chunk >> 3;
        int c = chunk & 7;
        cp_async16(sA + sw128((uint32_t)(r * 128 + c * 16)),
                   Ag + (size_t)(m0 + r) * IN_F + k0 + c * 8);
    }
#pragma unroll
    for (int i = 0; i < 8; i++) {
        int chunk = tid + i * 128;
        int r = chunk >> 3;
        int c = chunk & 7;
        cp_async16(sB + sw128((uint32_t)(r * 128 + c * 16)),
                   Bg + (size_t)(n0 + r) * IN_F + k0 + c * 8);
    }
}

// Load one ks-step's register fragments (a: 4 x ldmatrix.x4, b: 4 x ldmatrix.x4)
__device__ __forceinline__ void load_frags(uint32_t sA, uint32_t sB, int ks,
                                           int wm, int wn, int lane,
                                           uint32_t a[4][4], uint32_t b[8][2]) {
    const int cb = ks * 32 + ((lane >> 4) << 4);  // byte col within 128B row
#pragma unroll
    for (int mf = 0; mf < 4; mf++) {
        int r = wm * 64 + mf * 16 + (lane & 15);
        uint32_t addr = sA + sw128((uint32_t)(r * 128 + cb));
        asm volatile(
            "ldmatrix.sync.aligned.m8n8.x4.shared.b16 {%0,%1,%2,%3}, [%4];\n"
            : "=r"(a[mf][0]), "=r"(a[mf][1]), "=r"(a[mf][2]), "=r"(a[mf][3])
            : "r"(addr));
    }
#pragma unroll
    for (int p = 0; p < 4; p++) {
        int r = wn * 64 + p * 16 + (lane & 15);
        uint32_t addr = sB + sw128((uint32_t)(r * 128 + cb));
        uint32_t r0, r1, r2, r3;
        asm volatile(
            "ldmatrix.sync.aligned.m8n8.x4.shared.b16 {%0,%1,%2,%3}, [%4];\n"
            : "=r"(r0), "=r"(r1), "=r"(r2), "=r"(r3)
            : "r"(addr));
        // reg0: n[0..7] k[0..7], reg1: n[8..15] k[0..7],
        // reg2: n[0..7] k[8..15], reg3: n[8..15] k[8..15]
        b[p * 2 + 0][0] = r0; b[p * 2 + 0][1] = r2;
        b[p * 2 + 1][0] = r1; b[p * 2 + 1][1] = r3;
    }
}

__global__ void __launch_bounds__(128, 2)
gemm_kernel(float* __restrict__ C) {
    extern __shared__ char smem[];
    const __half* __restrict__ A = g_X;
    const __half* __restrict__ B = g_W;

    const int tid  = threadIdx.x;
    const int lane = tid & 31;
    const int warp = tid >> 5;
    const int wm   = warp & 1;     // 0..1 -> m offset wm*64
    const int wn   = warp >> 1;    // 0..1 -> n offset wn*64
    const int m0   = blockIdx.x * BM;
    const int n0   = blockIdx.y * BN;

    uint32_t sbase = (uint32_t)__cvta_generic_to_shared(smem);

    float acc[4][8][4];
#pragma unroll
    for (int i = 0; i < 4; i++)
#pragma unroll
        for (int j = 0; j < 8; j++)
#pragma unroll
            for (int k = 0; k < 4; k++) acc[i][j][k] = 0.0f;

#pragma unroll
    for (int s = 0; s < STAGES - 1; s++) {
        load_tiles(sbase + s * STAGE_BYTES, A, B, m0, n0, s * BK, tid);
        asm volatile("cp.async.commit_group;\n" ::: "memory");
    }

    uint32_t a[2][4][4];
    uint32_t b[2][8][2];

    // Prologue arrive: provides the 128 "stage free" tokens for kt=0's sync.
    asm volatile("bar.arrive 1, 256;" ::: "memory");

    for (int kt = 0; kt < KT; kt++) {
        asm volatile("cp.async.wait_group 1;\n" ::: "memory");
        // All warps done reading the stage about to be overwritten, and (with
        // the per-thread wait above) all threads' loads for stage kt landed.
        asm volatile("bar.sync 1, 256;" ::: "memory");

        int kn = kt + STAGES - 1;
        if (kn < KT) {
            load_tiles(sbase + (kn % STAGES) * STAGE_BYTES, A, B,
                       m0, n0, kn * BK, tid);
        }
        asm volatile("cp.async.commit_group;\n" ::: "memory");

        uint32_t sA = sbase + (kt % STAGES) * STAGE_BYTES;
        uint32_t sB = sA + STAGE_A_BYTES;

        // Software-pipelined fragments over the 4 ks steps
        load_frags(sA, sB, 0, wm, wn, lane, a[0], b[0]);
#pragma unroll
        for (int ks = 0; ks < 4; ks++) {
            int cur = ks & 1;
            if (ks < 3)
                load_frags(sA, sB, ks + 1, wm, wn, lane, a[cur ^ 1], b[cur ^ 1]);
            if (ks == 2) {
                // Last smem read of this stage just issued; signal early so
                // other warps' loop-top sync overlaps our ks=3 mma block.
                asm volatile("bar.arrive 1, 256;" ::: "memory");
            }
#pragma unroll
            for (int mf = 0; mf < 4; mf++) {
#pragma unroll
                for (int nf = 0; nf < 8; nf++) {
                    float* c = acc[mf][nf];
                    asm volatile(
                        "mma.sync.aligned.m16n8k16.row.col.f32.f16.f16.f32 "
                        "{%0,%1,%2,%3}, {%4,%5,%6,%7}, {%8,%9}, {%0,%1,%2,%3};\n"
                        : "+f"(c[0]), "+f"(c[1]), "+f"(c[2]), "+f"(c[3])
                        : "r"(a[cur][mf][0]), "r"(a[cur][mf][1]),
                          "r"(a[cur][mf][2]), "r"(a[cur][mf][3]),
                          "r"(b[cur][nf][0]), "r"(b[cur][nf][1]));
                }
            }
        }
    }

    // Epilogue: direct f32 stores (float2), every element covered.
#pragma unroll
    for (int mf = 0; mf < 4; mf++) {
#pragma unroll
        for (int nf = 0; nf < 8; nf++) {
            int m = m0 + wm * 64 + mf * 16 + (lane >> 2);
            int n = n0 + wn * 64 + nf * 8 + (lane & 3) * 2;
            float2* p0 = reinterpret_cast<float2*>(C + (size_t)m * OUT_F + n);
            *p0 = make_float2(acc[mf][nf][0], acc[mf][nf][1]);
            float2* p1 = reinterpret_cast<float2*>(C + (size_t)(m + 8) * OUT_F + n);
            *p1 = make_float2(acc[mf][nf][2], acc[mf][nf][3]);
        }
    }
}

// ---------------------------------------------------------------------------
extern "C" void kernel_launch(void* const* d_in, const int* in_sizes, int n_in,
                              void* d_out, int out_size) {
    (void)n_in; (void)out_size;
    float* out = (float*)d_out;   // [M, OUT_F] f32

    const int n_x = in_sizes[0];            // x element count (f32)
    const int M   = n_x / IN_F;             // 4096

    // 1) Fused prep: convert x -> fp16 g_X  +  dequant W -> fp16 g_W
    {
        int nconv = (n_x / 8 + 255) / 256;                  // convert blocks
        int ndeq  = (OUT_F * (IN_F / 8) + 255) / 256;       // dequant blocks
        prep_kernel<<<nconv + ndeq, 256>>>(
            (const float4*)d_in[0], n_x, nconv,
            (const int4*)d_in[1], (const float*)d_in[2], (const int*)d_in[3]);
    }

    // 2) Tensor-core GEMM (2 CTAs/SM)
    cudaFuncSetAttribute(gemm_kernel,
                         cudaFuncAttributeMaxDynamicSharedMemorySize,
                         STAGES * STAGE_BYTES);
    dim3 grid(M / BM, OUT_F / BN);   // (32, 86): M fastest -> N-band L2 reuse
    gemm_kernel<<<grid, 128, STAGES * STAGE_BYTES>>>(out);
}

// round 11
// speedup vs baseline: 1.1394x; 1.0046x over previous
#include <cuda_runtime.h>
#include <cuda_fp16.h>
#include <cstdint>

// Problem constants (fixed by the dataset)
#define IN_F   4096
#define OUT_F  11008
#define GROUPS 32       // IN_F / 128
#define BM 128
#define BN 128
#define BK 64           // k-halves per stage (128 bytes per row)
#define STAGES 3
#define STAGE_A_BYTES (BM * 128)                       // 16384
#define STAGE_BYTES   (STAGE_A_BYTES + BN * 128)       // 32768
#define KT (IN_F / BK)  // 64

// Dequantized weights, fp16, [OUT_F][IN_F] row-major (K contiguous).
__device__ __half g_W[(size_t)OUT_F * IN_F];
// Activations converted to fp16, [M][IN_F].
__device__ __half g_X[(size_t)4096 * IN_F];

// ---------------------------------------------------------------------------
// Fused prep: blocks [0, nconv) convert x f32->fp16; the rest dequantize W.
// ---------------------------------------------------------------------------
__global__ void prep_kernel(const float4* __restrict__ xin, int n_x, int nconv,
                            const int4* __restrict__ qw,
                            const float* __restrict__ scales,
                            const int* __restrict__ qz) {
    if ((int)blockIdx.x < nconv) {
        int i = (blockIdx.x * blockDim.x + threadIdx.x) * 8;
        if (i >= n_x) return;
        float4 a = xin[i / 4];
        float4 b = xin[i / 4 + 1];
        __half2 h[4];
        h[0] = __floats2half2_rn(a.x, a.y);
        h[1] = __floats2half2_rn(a.z, a.w);
        h[2] = __floats2half2_rn(b.x, b.y);
        h[3] = __floats2half2_rn(b.z, b.w);
        *reinterpret_cast<uint4*>(g_X + i) = *reinterpret_cast<uint4*>(h);
    } else {
        const int JP = IN_F / 8;  // 512 int4-chunks per output row
        int idx = (blockIdx.x - nconv) * blockDim.x + threadIdx.x;
        if (idx >= OUT_F * JP) return;

        int o  = idx / JP;
        int jq = idx - o * JP;
        int g  = jq >> 4;           // group = (jq*8)/128

        int4 v = qw[idx];
        int zb = qz[o * (GROUPS / 2) + (g >> 1)];
        int z  = (g & 1) ? ((zb >> 4) & 15) : (zb & 15);
        float s = scales[o * GROUPS + g];

        int q[4] = {v.x, v.y, v.z, v.w};
        __half2 h[4];
#pragma unroll
        for (int t = 0; t < 4; t++) {
            float w0 = (float)((q[t] & 15) - z) * s;
            float w1 = (float)(((q[t] >> 4) & 15) - z) * s;
            h[t] = __floats2half2_rn(w0, w1);
        }
        *reinterpret_cast<uint4*>(g_W + (size_t)idx * 8) = *reinterpret_cast<uint4*>(h);
    }
}

// ---------------------------------------------------------------------------
// GEMM: C[M][OUT_F] (f32) = A[M][IN_F] (f16) * W^T
// TN mma.sync.m16n8k16. BM=BN=128 BK=64, 3-stage cp.async, SW128 smem,
// 4 warps (2x2), warp tile 64x64, 2 CTAs/SM, reg fragment pipelining,
// split named barrier; global prefetch interleaved into the 4 ks blocks.
// ---------------------------------------------------------------------------
__device__ __forceinline__ uint32_t sw128(uint32_t o) {
    return o ^ ((o >> 3) & 0x70);
}

__device__ __forceinline__ void cp_async16(uint32_t saddr, const void* gptr) {
    asm volatile("cp.async.cg.shared.global [%0], [%1], 16;\n"
                 :: "r"(saddr), "l"(gptr) : "memory");
}

// One quarter of a k-stage load: 2 A-chunks + 2 B-chunks per thread.
__device__ __forceinline__ void load_quarter(uint32_t sA,
                                             const __half* __restrict__ Ag,
                                             const __half* __restrict__ Bg,
                                             int m0, int n0, int k0, int tid,
                                             int q) {
    uint32_t sB = sA + STAGE_A_BYTES;
#pragma unroll
    for (int i = 2 * q; i < 2 * q + 2; i++) {
        int chunk = tid + i * 128;
        int r = chunk >> 3;
        int c = chunk & 7;
        cp_async16(sA + sw128((uint32_t)(r * 128 + c * 16)),
                   Ag + (size_t)(m0 + r) * IN_F + k0 + c * 8);
    }
#pragma unroll
    for (int i = 2 * q; i < 2 * q + 2; i++) {
        int chunk = tid + i * 128;
        int r = chunk >> 3;
        int c = chunk & 7;
        cp_async16(sB + sw128((uint32_t)(r * 128 + c * 16)),
                   Bg + (size_t)(n0 + r) * IN_F + k0 + c * 8);
    }
}

// Full stage load (prologue only).
__device__ __forceinline__ void load_tiles(uint32_t sA,
                                           const __half* __restrict__ Ag,
                                           const __half* __restrict__ Bg,
                                           int m0, int n0, int k0, int tid) {
#pragma unroll
    for (int q = 0; q < 4; q++)
        load_quarter(sA, Ag, Bg, m0, n0, k0, tid, q);
}

// Load one ks-step's register fragments (a: 4 x ldmatrix.x4, b: 4 x ldmatrix.x4)
__device__ __forceinline__ void load_frags(uint32_t sA, uint32_t sB, int ks,
                                           int wm, int wn, int lane,
                                           uint32_t a[4][4], uint32_t b[8][2]) {
    const int cb = ks * 32 + ((lane >> 4) << 4);  // byte col within 128B row
#pragma unroll
    for (int mf = 0; mf < 4; mf++) {
        int r = wm * 64 + mf * 16 + (lane & 15);
        uint32_t addr = sA + sw128((uint32_t)(r * 128 + cb));
        asm volatile(
            "ldmatrix.sync.aligned.m8n8.x4.shared.b16 {%0,%1,%2,%3}, [%4];\n"
            : "=r"(a[mf][0]), "=r"(a[mf][1]), "=r"(a[mf][2]), "=r"(a[mf][3])
            : "r"(addr));
    }
#pragma unroll
    for (int p = 0; p < 4; p++) {
        int r = wn * 64 + p * 16 + (lane & 15);
        uint32_t addr = sB + sw128((uint32_t)(r * 128 + cb));
        uint32_t r0, r1, r2, r3;
        asm volatile(
            "ldmatrix.sync.aligned.m8n8.x4.shared.b16 {%0,%1,%2,%3}, [%4];\n"
            : "=r"(r0), "=r"(r1), "=r"(r2), "=r"(r3)
            : "r"(addr));
        // reg0: n[0..7] k[0..7], reg1: n[8..15] k[0..7],
        // reg2: n[0..7] k[8..15], reg3: n[8..15] k[8..15]
        b[p * 2 + 0][0] = r0; b[p * 2 + 0][1] = r2;
        b[p * 2 + 1][0] = r1; b[p * 2 + 1][1] = r3;
    }
}

__global__ void __launch_bounds__(128, 2)
gemm_kernel(float* __restrict__ C) {
    extern __shared__ char smem[];
    const __half* __restrict__ A = g_X;
    const __half* __restrict__ B = g_W;

    const int tid  = threadIdx.x;
    const int lane = tid & 31;
    const int warp = tid >> 5;
    const int wm   = warp & 1;     // 0..1 -> m offset wm*64
    const int wn   = warp >> 1;    // 0..1 -> n offset wn*64
    const int m0   = blockIdx.x * BM;
    const int n0   = blockIdx.y * BN;

    uint32_t sbase = (uint32_t)__cvta_generic_to_shared(smem);

    float acc[4][8][4];
#pragma unroll
    for (int i = 0; i < 4; i++)
#pragma unroll
        for (int j = 0; j < 8; j++)
#pragma unroll
            for (int k = 0; k < 4; k++) acc[i][j][k] = 0.0f;

#pragma unroll
    for (int s = 0; s < STAGES - 1; s++) {
        load_tiles(sbase + s * STAGE_BYTES, A, B, m0, n0, s * BK, tid);
        asm volatile("cp.async.commit_group;\n" ::: "memory");
    }

    uint32_t a[2][4][4];
    uint32_t b[2][8][2];

    // Prologue arrive: provides the "stage free" tokens for kt=0's sync.
    asm volatile("bar.arrive 1, 256;" ::: "memory");

    for (int kt = 0; kt < KT; kt++) {
        asm volatile("cp.async.wait_group 1;\n" ::: "memory");
        // All warps done reading the stage about to be overwritten, and (with
        // the per-thread wait above) all threads' loads for stage kt landed.
        asm volatile("bar.sync 1, 256;" ::: "memory");

        const int kn = kt + STAGES - 1;
        const bool do_load = (kn < KT);
        uint32_t sLoad = sbase + (kn % STAGES) * STAGE_BYTES;
        const int kload = kn * BK;

        uint32_t sA = sbase + (kt % STAGES) * STAGE_BYTES;
        uint32_t sB = sA + STAGE_A_BYTES;

        // Software-pipelined fragments; prefetch quarters interleaved per ks.
        load_frags(sA, sB, 0, wm, wn, lane, a[0], b[0]);
#pragma unroll
        for (int ks = 0; ks < 4; ks++) {
            int cur = ks & 1;
            if (ks < 3)
                load_frags(sA, sB, ks + 1, wm, wn, lane, a[cur ^ 1], b[cur ^ 1]);
            if (do_load)
                load_quarter(sLoad, A, B, m0, n0, kload, tid, ks);
            if (ks == 2) {
                // Last smem read of this stage just issued; signal early so
                // other warps' loop-top sync overlaps our ks=3 mma block.
                asm volatile("bar.arrive 1, 256;" ::: "memory");
            }
#pragma unroll
            for (int mf = 0; mf < 4; mf++) {
#pragma unroll
                for (int nf = 0; nf < 8; nf++) {
                    float* c = acc[mf][nf];
                    asm volatile(
                        "mma.sync.aligned.m16n8k16.row.col.f32.f16.f16.f32 "
                        "{%0,%1,%2,%3}, {%4,%5,%6,%7}, {%8,%9}, {%0,%1,%2,%3};\n"
                        : "+f"(c[0]), "+f"(c[1]), "+f"(c[2]), "+f"(c[3])
                        : "r"(a[cur][mf][0]), "r"(a[cur][mf][1]),
                          "r"(a[cur][mf][2]), "r"(a[cur][mf][3]),
                          "r"(b[cur][nf][0]), "r"(b[cur][nf][1]));
                }
            }
        }
        asm volatile("cp.async.commit_group;\n" ::: "memory");
    }

    // Epilogue: direct f32 stores (float2), every element covered.
#pragma unroll
    for (int mf = 0; mf < 4; mf++) {
#pragma unroll
        for (int nf = 0; nf < 8; nf++) {
            int m = m0 + wm * 64 + mf * 16 + (lane >> 2);
            int n = n0 + wn * 64 + nf * 8 + (lane & 3) * 2;
            float2* p0 = reinterpret_cast<float2*>(C + (size_t)m * OUT_F + n);
            *p0 = make_float2(acc[mf][nf][0], acc[mf][nf][1]);
            float2* p1 = reinterpret_cast<float2*>(C + (size_t)(m + 8) * OUT_F + n);
            *p1 = make_float2(acc[mf][nf][2], acc[mf][nf][3]);
        }
    }
}

// ---------------------------------------------------------------------------
extern "C" void kernel_launch(void* const* d_in, const int* in_sizes, int n_in,
                              void* d_out, int out_size) {
    (void)n_in; (void)out_size;
    float* out = (float*)d_out;   // [M, OUT_F] f32

    const int n_x = in_sizes[0];            // x element count (f32)
    const int M   = n_x / IN_F;             // 4096

    // 1) Fused prep: convert x -> fp16 g_X  +  dequant W -> fp16 g_W
    {
        int nconv = (n_x / 8 + 255) / 256;                  // convert blocks
        int ndeq  = (OUT_F * (IN_F / 8) + 255) / 256;       // dequant blocks
        prep_kernel<<<nconv + ndeq, 256>>>(
            (const float4*)d_in[0], n_x, nconv,
            (const int4*)d_in[1], (const float*)d_in[2], (const int*)d_in[3]);
    }

    // 2) Tensor-core GEMM (2 CTAs/SM)
    cudaFuncSetAttribute(gemm_kernel,
                         cudaFuncAttributeMaxDynamicSharedMemorySize,
                         STAGES * STAGE_BYTES);
    dim3 grid(M / BM, OUT_F / BN);   // (32, 86): M fastest -> N-band L2 reuse
    gemm_kernel<<<grid, 128, STAGES * STAGE_BYTES>>>(out);
}